// round 1
// baseline (speedup 1.0000x reference)
#include <cuda_runtime.h>
#include <math.h>

// Problem constants
#define CB  2
#define CS  2048
#define CD  768
#define CH  12
#define CDK 64
#define CM  (CB * CS)            // 4096 rows for projections
#define BHS (CB * CH * CS)       // 49152 attention rows
#define OUT_ELEMS (CB * CS * CD) // 3145728 (output tensor), attn follows in d_out

// Scratch (static device allocations — no cudaMalloc allowed)
__device__ float  g_Q[CB * CH * CS * CDK];
__device__ float  g_K[CB * CH * CS * CDK];
__device__ float  g_V[CB * CH * CS * CDK];
__device__ float  g_ctx[CB * CH * CS * CDK];
__device__ float2 g_stats[BHS];

// ---------------------------------------------------------------------------
// Kernel 1: QKV projection.  out[b,h,s,dk] = sum_k X[b,s,k] * W[h*64+dk, k]
// Classic 128x128x8 SGEMM, 256 threads, 8x8 microtile.
// ---------------------------------------------------------------------------
__global__ void __launch_bounds__(256) proj_qkv_kernel(
    const float* __restrict__ X, const float* __restrict__ W,
    float* __restrict__ out)
{
    __shared__ float As[8][128];
    __shared__ float Bs[8][128];
    const int tid = threadIdx.x;
    const int tx = tid & 15, ty = tid >> 4;
    const int m0 = blockIdx.y * 128, n0 = blockIdx.x * 128;
    const int lr = tid >> 1;        // 0..127
    const int lc = (tid & 1) * 4;   // 0 or 4

    float acc[8][8];
#pragma unroll
    for (int i = 0; i < 8; i++)
#pragma unroll
        for (int j = 0; j < 8; j++) acc[i][j] = 0.f;

    const float* Ag = X + (m0 + lr) * CD + lc;
    const float* Bg = W + (n0 + lr) * CD + lc;

    for (int k0 = 0; k0 < CD; k0 += 8) {
        float4 av = *(const float4*)(Ag + k0);
        float4 bv = *(const float4*)(Bg + k0);
        __syncthreads();
        As[lc + 0][lr] = av.x; As[lc + 1][lr] = av.y;
        As[lc + 2][lr] = av.z; As[lc + 3][lr] = av.w;
        Bs[lc + 0][lr] = bv.x; Bs[lc + 1][lr] = bv.y;
        Bs[lc + 2][lr] = bv.z; Bs[lc + 3][lr] = bv.w;
        __syncthreads();
#pragma unroll
        for (int k = 0; k < 8; k++) {
            float a[8], b[8];
            *(float4*)&a[0] = *(const float4*)&As[k][ty * 8];
            *(float4*)&a[4] = *(const float4*)&As[k][ty * 8 + 4];
            *(float4*)&b[0] = *(const float4*)&Bs[k][tx * 8];
            *(float4*)&b[4] = *(const float4*)&Bs[k][tx * 8 + 4];
#pragma unroll
            for (int i = 0; i < 8; i++)
#pragma unroll
                for (int j = 0; j < 8; j++)
                    acc[i][j] += a[i] * b[j];
        }
    }

    // Scatter to [B,H,S,DK]
#pragma unroll
    for (int i = 0; i < 8; i++) {
        int m = m0 + ty * 8 + i;
        int b = m >> 11, s = m & (CS - 1);
#pragma unroll
        for (int j = 0; j < 8; j++) {
            int n = n0 + tx * 8 + j;
            int h = n >> 6, dk = n & 63;
            out[((b * CH + h) * CS + s) * CDK + dk] = acc[i][j];
        }
    }
}

// ---------------------------------------------------------------------------
// Kernel 2: scores = Q·K^T/8 + pos_bias, masked. Writes raw scores into the
// attn region of d_out. K dim = 64, processed in 8-wide shared tiles.
// ---------------------------------------------------------------------------
__global__ void __launch_bounds__(256) scores_kernel(
    const float* __restrict__ Q, const float* __restrict__ K,
    const float* __restrict__ pos_bias, const int* __restrict__ mask,
    float* __restrict__ raw)
{
    __shared__ float As[8][128];
    __shared__ float Bs[8][128];
    const int tid = threadIdx.x;
    const int tx = tid & 15, ty = tid >> 4;
    const int bh = blockIdx.z;
    const int b = bh / CH, h = bh - b * CH;
    const int q0 = blockIdx.y * 128, kk0 = blockIdx.x * 128;
    const int lr = tid >> 1;
    const int lc = (tid & 1) * 4;

    float acc[8][8];
#pragma unroll
    for (int i = 0; i < 8; i++)
#pragma unroll
        for (int j = 0; j < 8; j++) acc[i][j] = 0.f;

    const float* Qg = Q + (bh * CS + q0 + lr) * CDK + lc;
    const float* Kg = K + (bh * CS + kk0 + lr) * CDK + lc;

    for (int k0 = 0; k0 < CDK; k0 += 8) {
        float4 av = *(const float4*)(Qg + k0);
        float4 bv = *(const float4*)(Kg + k0);
        __syncthreads();
        As[lc + 0][lr] = av.x; As[lc + 1][lr] = av.y;
        As[lc + 2][lr] = av.z; As[lc + 3][lr] = av.w;
        Bs[lc + 0][lr] = bv.x; Bs[lc + 1][lr] = bv.y;
        Bs[lc + 2][lr] = bv.z; Bs[lc + 3][lr] = bv.w;
        __syncthreads();
#pragma unroll
        for (int k = 0; k < 8; k++) {
            float a[8], bb[8];
            *(float4*)&a[0]  = *(const float4*)&As[k][ty * 8];
            *(float4*)&a[4]  = *(const float4*)&As[k][ty * 8 + 4];
            *(float4*)&bb[0] = *(const float4*)&Bs[k][tx * 8];
            *(float4*)&bb[4] = *(const float4*)&Bs[k][tx * 8 + 4];
#pragma unroll
            for (int i = 0; i < 8; i++)
#pragma unroll
                for (int j = 0; j < 8; j++)
                    acc[i][j] += a[i] * bb[j];
        }
    }

    const int kc0 = kk0 + tx * 8;
#pragma unroll
    for (int i = 0; i < 8; i++) {
        int qq = q0 + ty * 8 + i;
        const float* pbr = pos_bias + (h * CS + qq) * CS + kc0;
        const int*   mkr = mask + (b * CS + qq) * CS + kc0;
        float*       rr  = raw + (bh * CS + qq) * CS + kc0;
        float4 p0 = *(const float4*)(pbr);
        float4 p1 = *(const float4*)(pbr + 4);
        int4   m0v = *(const int4*)(mkr);
        int4   m1v = *(const int4*)(mkr + 4);
        float4 o0, o1;
        o0.x = (m0v.x == 0) ? -1e9f : acc[i][0] * 0.125f + p0.x;
        o0.y = (m0v.y == 0) ? -1e9f : acc[i][1] * 0.125f + p0.y;
        o0.z = (m0v.z == 0) ? -1e9f : acc[i][2] * 0.125f + p0.z;
        o0.w = (m0v.w == 0) ? -1e9f : acc[i][3] * 0.125f + p0.w;
        o1.x = (m1v.x == 0) ? -1e9f : acc[i][4] * 0.125f + p1.x;
        o1.y = (m1v.y == 0) ? -1e9f : acc[i][5] * 0.125f + p1.y;
        o1.z = (m1v.z == 0) ? -1e9f : acc[i][6] * 0.125f + p1.z;
        o1.w = (m1v.w == 0) ? -1e9f : acc[i][7] * 0.125f + p1.w;
        *(float4*)(rr)     = o0;
        *(float4*)(rr + 4) = o1;
    }
}

// ---------------------------------------------------------------------------
// Kernel 3: per-row max and 1/sum(exp(s-max)).  One 256-thread block per row.
// ---------------------------------------------------------------------------
__global__ void __launch_bounds__(256) stats_kernel(
    const float* __restrict__ raw, float2* __restrict__ stats)
{
    __shared__ float red[256];
    const int r = blockIdx.x;
    const int tid = threadIdx.x;
    const float* p = raw + r * CS;

    float v[8];
    *(float4*)&v[0] = *(const float4*)(p + tid * 8);
    *(float4*)&v[4] = *(const float4*)(p + tid * 8 + 4);

    float mx = v[0];
#pragma unroll
    for (int i = 1; i < 8; i++) mx = fmaxf(mx, v[i]);
    red[tid] = mx;
    __syncthreads();
    for (int s = 128; s > 0; s >>= 1) {
        if (tid < s) red[tid] = fmaxf(red[tid], red[tid + s]);
        __syncthreads();
    }
    mx = red[0];
    __syncthreads();

    float se = 0.f;
#pragma unroll
    for (int i = 0; i < 8; i++) se += __expf(v[i] - mx);
    red[tid] = se;
    __syncthreads();
    for (int s = 128; s > 0; s >>= 1) {
        if (tid < s) red[tid] += red[tid + s];
        __syncthreads();
    }
    if (tid == 0) stats[r] = make_float2(mx, 1.f / red[0]);
}

// ---------------------------------------------------------------------------
// Kernel 4: normalize attn in place AND compute ctx = attn @ V.
// Block = (bh, 128 q-rows). 256 threads, 8x4 microtile over [128 x 64].
// ---------------------------------------------------------------------------
__global__ void __launch_bounds__(256) pv_kernel(
    float* __restrict__ attn, const float* __restrict__ V,
    const float2* __restrict__ stats, float* __restrict__ ctx)
{
    __shared__ float Ps[16][128];
    __shared__ float Vs[16][64];
    __shared__ float smax[128], sinv[128];
    const int tid = threadIdx.x;
    const int tx = tid & 15, ty = tid >> 4;
    const int bh = blockIdx.y;
    const int q0 = blockIdx.x * 128;

    if (tid < 128) {
        float2 st = stats[bh * CS + q0 + tid];
        smax[tid] = st.x;
        sinv[tid] = st.y;
    }
    __syncthreads();

    const int lr = tid >> 1;        // 0..127 (q row within tile)
    const int lc = (tid & 1) * 8;   // 0 or 8 (k offset within 16-tile)
    float* rowbase = attn + (bh * CS + q0) * CS;
    const float* Vb = V + bh * CS * CDK;
    const float myMax = smax[lr];
    const float myInv = sinv[lr];

    float acc[8][4];
#pragma unroll
    for (int i = 0; i < 8; i++)
#pragma unroll
        for (int j = 0; j < 4; j++) acc[i][j] = 0.f;

    const int vkr = tid >> 4;        // 0..15
    const int vng = (tid & 15) * 4;  // 0..60

    for (int k0 = 0; k0 < CS; k0 += 16) {
        float4 r0 = *(const float4*)(rowbase + lr * CS + k0 + lc);
        float4 r1 = *(const float4*)(rowbase + lr * CS + k0 + lc + 4);
        float4 p0, p1;
        p0.x = __expf(r0.x - myMax) * myInv;
        p0.y = __expf(r0.y - myMax) * myInv;
        p0.z = __expf(r0.z - myMax) * myInv;
        p0.w = __expf(r0.w - myMax) * myInv;
        p1.x = __expf(r1.x - myMax) * myInv;
        p1.y = __expf(r1.y - myMax) * myInv;
        p1.z = __expf(r1.z - myMax) * myInv;
        p1.w = __expf(r1.w - myMax) * myInv;
        // write normalized attn back (this is the final attn output)
        *(float4*)(rowbase + lr * CS + k0 + lc)     = p0;
        *(float4*)(rowbase + lr * CS + k0 + lc + 4) = p1;
        float4 vv = *(const float4*)(Vb + (k0 + vkr) * CDK + vng);
        __syncthreads();
        Ps[lc + 0][lr] = p0.x; Ps[lc + 1][lr] = p0.y;
        Ps[lc + 2][lr] = p0.z; Ps[lc + 3][lr] = p0.w;
        Ps[lc + 4][lr] = p1.x; Ps[lc + 5][lr] = p1.y;
        Ps[lc + 6][lr] = p1.z; Ps[lc + 7][lr] = p1.w;
        *(float4*)&Vs[vkr][vng] = vv;
        __syncthreads();
#pragma unroll
        for (int k = 0; k < 16; k++) {
            float a[8];
            *(float4*)&a[0] = *(const float4*)&Ps[k][ty * 8];
            *(float4*)&a[4] = *(const float4*)&Ps[k][ty * 8 + 4];
            float4 bv = *(const float4*)&Vs[k][tx * 4];
#pragma unroll
            for (int i = 0; i < 8; i++) {
                acc[i][0] += a[i] * bv.x;
                acc[i][1] += a[i] * bv.y;
                acc[i][2] += a[i] * bv.z;
                acc[i][3] += a[i] * bv.w;
            }
        }
    }

#pragma unroll
    for (int i = 0; i < 8; i++) {
        float4 o;
        o.x = acc[i][0]; o.y = acc[i][1]; o.z = acc[i][2]; o.w = acc[i][3];
        *(float4*)(ctx + (bh * CS + q0 + ty * 8 + i) * CDK + tx * 4) = o;
    }
}

// ---------------------------------------------------------------------------
// Kernel 5: output projection. out[b,s,n] = sum_d ctx[b,h(d),s,dk(d)]*Wo[n,d] + bo[n]
// ---------------------------------------------------------------------------
__global__ void __launch_bounds__(256) outproj_kernel(
    const float* __restrict__ ctx, const float* __restrict__ W,
    const float* __restrict__ bias, float* __restrict__ out)
{
    __shared__ float As[8][128];
    __shared__ float Bs[8][128];
    const int tid = threadIdx.x;
    const int tx = tid & 15, ty = tid >> 4;
    const int m0 = blockIdx.y * 128, n0 = blockIdx.x * 128;
    const int lr = tid >> 1;
    const int lc = (tid & 1) * 4;

    float acc[8][8];
#pragma unroll
    for (int i = 0; i < 8; i++)
#pragma unroll
        for (int j = 0; j < 8; j++) acc[i][j] = 0.f;

    const int mrow = m0 + lr;
    const int bb = mrow >> 11, ss = mrow & (CS - 1);
    const float* Abase = ctx + (bb * CH * CS + ss) * CDK;
    const float* Bg = W + (n0 + lr) * CD + lc;

    for (int k0 = 0; k0 < CD; k0 += 8) {
        int kk = k0 + lc;
        int h = kk >> 6, dk = kk & 63;
        float4 av = *(const float4*)(Abase + h * CS * CDK + dk);
        float4 bv = *(const float4*)(Bg + k0);
        __syncthreads();
        As[lc + 0][lr] = av.x; As[lc + 1][lr] = av.y;
        As[lc + 2][lr] = av.z; As[lc + 3][lr] = av.w;
        Bs[lc + 0][lr] = bv.x; Bs[lc + 1][lr] = bv.y;
        Bs[lc + 2][lr] = bv.z; Bs[lc + 3][lr] = bv.w;
        __syncthreads();
#pragma unroll
        for (int k = 0; k < 8; k++) {
            float a[8], b[8];
            *(float4*)&a[0] = *(const float4*)&As[k][ty * 8];
            *(float4*)&a[4] = *(const float4*)&As[k][ty * 8 + 4];
            *(float4*)&b[0] = *(const float4*)&Bs[k][tx * 8];
            *(float4*)&b[4] = *(const float4*)&Bs[k][tx * 8 + 4];
#pragma unroll
            for (int i = 0; i < 8; i++)
#pragma unroll
                for (int j = 0; j < 8; j++)
                    acc[i][j] += a[i] * b[j];
        }
    }

#pragma unroll
    for (int i = 0; i < 8; i++) {
        int m = m0 + ty * 8 + i;
#pragma unroll
        for (int j = 0; j < 8; j++) {
            int n = n0 + tx * 8 + j;
            out[m * CD + n] = acc[i][j] + bias[n];
        }
    }
}

// ---------------------------------------------------------------------------
extern "C" void kernel_launch(void* const* d_in, const int* in_sizes, int n_in,
                              void* d_out, int out_size)
{
    (void)in_sizes; (void)n_in; (void)out_size;
    const float* query    = (const float*)d_in[0];
    const float* key      = (const float*)d_in[1];
    const float* value    = (const float*)d_in[2];
    const int*   mask     = (const int*)d_in[3];
    const float* pos_bias = (const float*)d_in[4];
    const float* Wq       = (const float*)d_in[5];
    const float* Wk       = (const float*)d_in[6];
    const float* Wv       = (const float*)d_in[7];
    const float* Wo       = (const float*)d_in[8];
    const float* bo       = (const float*)d_in[9];

    float* out  = (float*)d_out;
    float* attn = out + OUT_ELEMS;

    float *pQ, *pK, *pV, *pC;
    float2* pSt;
    cudaGetSymbolAddress((void**)&pQ,  g_Q);
    cudaGetSymbolAddress((void**)&pK,  g_K);
    cudaGetSymbolAddress((void**)&pV,  g_V);
    cudaGetSymbolAddress((void**)&pC,  g_ctx);
    cudaGetSymbolAddress((void**)&pSt, g_stats);

    dim3 gProj(CD / 128, CM / 128);   // (6, 32)
    proj_qkv_kernel<<<gProj, 256>>>(query, Wq, pQ);
    proj_qkv_kernel<<<gProj, 256>>>(key,   Wk, pK);
    proj_qkv_kernel<<<gProj, 256>>>(value, Wv, pV);

    dim3 gScores(CS / 128, CS / 128, CB * CH);  // (16,16,24)
    scores_kernel<<<gScores, 256>>>(pQ, pK, pos_bias, mask, attn);

    stats_kernel<<<BHS, 256>>>(attn, pSt);

    dim3 gPV(CS / 128, CB * CH);      // (16, 24)
    pv_kernel<<<gPV, 256>>>(attn, pV, pSt, pC);

    outproj_kernel<<<gProj, 256>>>(pC, Wo, bo, out);
}